// round 14
// baseline (speedup 1.0000x reference)
#include <cuda_runtime.h>
#include <math.h>
#include <cstdint>

#define LSEQ   2048
#define NB     4
#define DMODEL 1024
#define NH     16
#define HSIZE  64
#define MROWS  (NB*LSEQ)   // 8192

// Scratch (allocation-free rule: __device__ globals)
__device__ float g_Q[(size_t)NB*NH*LSEQ*HSIZE];
__device__ float g_K[(size_t)NB*NH*LSEQ*HSIZE];
__device__ float g_V[(size_t)NB*NH*LSEQ*HSIZE];
__device__ float g_Y[(size_t)MROWS*DMODEL];

// ---------------------------------------------------------------------------
// Packed fp32x2 helpers (Blackwell family-level PTX, compute_103-safe)
// ---------------------------------------------------------------------------
__device__ __forceinline__ uint64_t f2pk(float lo, float hi) {
    uint64_t r;
    asm("mov.b64 %0, {%1, %2};"
        : "=l"(r) : "r"(__float_as_uint(lo)), "r"(__float_as_uint(hi)));
    return r;
}
__device__ __forceinline__ void f2unpk(uint64_t v, float& lo, float& hi) {
    uint32_t a, b;
    asm("mov.b64 {%0, %1}, %2;" : "=r"(a), "=r"(b) : "l"(v));
    lo = __uint_as_float(a);
    hi = __uint_as_float(b);
}
__device__ __forceinline__ void ffma2(uint64_t& d, uint64_t a, uint64_t b) {
    asm("fma.rn.f32x2 %0, %1, %2, %0;" : "+l"(d) : "l"(a), "l"(b));
}
__device__ __forceinline__ uint64_t fadd2(uint64_t a, uint64_t b) {
    uint64_t r;
    asm("add.rn.f32x2 %0, %1, %2;" : "=l"(r) : "l"(a), "l"(b));
    return r;
}
__device__ __forceinline__ uint64_t fmul2(uint64_t a, uint64_t b) {
    uint64_t r;
    asm("mul.rn.f32x2 %0, %1, %2;" : "=l"(r) : "l"(a), "l"(b));
    return r;
}

// ---------------------------------------------------------------------------
// Kernel 1: qkv = x @ W_attn + b_attn.  PERSISTENT grid: 256 CTAs x 6 tiles
// (1536 total, perfectly balanced, single wave at occ 2).
// Per-tile body identical to R12 (quad layout + f32x2, double-buffered).
// ---------------------------------------------------------------------------
__global__ __launch_bounds__(256, 2) void gemm_qkv_kernel(
    const float* __restrict__ X, const float* __restrict__ W,
    const float* __restrict__ bias)
{
    __shared__ float As[2][8][128];
    __shared__ float Bs[2][8][128];
    const int tid  = threadIdx.x;
    const int wid  = tid >> 5;
    const int lane = tid & 31;
    const int wm   = wid >> 2;
    const int wn   = wid & 3;
    const int lr   = lane >> 2;
    const int lc   = lane & 3;
    const int aBase = wm*64 + lr*4;
    const int bBase = wn*32 + lc*4;

    const int aRow = tid >> 1;
    const int aCol = (tid & 1) << 2;
    const int bRow = tid >> 5;
    const int bCol = (tid & 31) << 2;

    for (int tile = blockIdx.x; tile < 1536; tile += 256) {
        const int m0 = (tile / 12) * 128;          // 64 m-tiles
        const int n0 = (tile % 12) * 256;          // pair tiles in n for loop
        // process two adjacent 128-wide n tiles? No — keep 1:1 mapping:
        // (reverted to single-tile body; 1536 = 64 x 24)
        const int n0s = (tile % 24) * 128;
        const int m0s = (tile / 24) * 128;
        (void)m0; (void)n0;

        const float* Ap = X + (size_t)(m0s + aRow) * DMODEL + aCol;
        const float* Bp = W + (size_t)bRow * 3072 + n0s + bCol;

        uint64_t acc2[8][4];
        #pragma unroll
        for (int i = 0; i < 8; i++)
            #pragma unroll
            for (int jp = 0; jp < 4; jp++) acc2[i][jp] = 0ull;

        __syncthreads();   // previous tile's smem fully consumed
        {
            float4 av = *(const float4*)(Ap);
            float4 bv = *(const float4*)(Bp);
            As[0][aCol+0][aRow] = av.x;
            As[0][aCol+1][aRow] = av.y;
            As[0][aCol+2][aRow] = av.z;
            As[0][aCol+3][aRow] = av.w;
            *(float4*)&Bs[0][bRow][bCol] = bv;
        }
        __syncthreads();

        const int NT = DMODEL / 8;
        for (int t = 0; t < NT; t++) {
            const int buf = t & 1;
            float4 anext, bnext;
            if (t + 1 < NT) {
                anext = *(const float4*)(Ap + (t+1)*8);
                bnext = *(const float4*)(Bp + (size_t)(t+1)*8*3072);
            }
            #pragma unroll
            for (int kk = 0; kk < 8; kk++) {
                float a[8], b[8];
                *(float4*)&a[0] = *(const float4*)&As[buf][kk][aBase];
                *(float4*)&a[4] = *(const float4*)&As[buf][kk][aBase + 32];
                *(float4*)&b[0] = *(const float4*)&Bs[buf][kk][bBase];
                *(float4*)&b[4] = *(const float4*)&Bs[buf][kk][bBase + 16];
                uint64_t b2[4];
                #pragma unroll
                for (int jp = 0; jp < 4; jp++) b2[jp] = f2pk(b[2*jp], b[2*jp+1]);
                #pragma unroll
                for (int i = 0; i < 8; i++) {
                    const uint64_t a2 = f2pk(a[i], a[i]);
                    #pragma unroll
                    for (int jp = 0; jp < 4; jp++)
                        ffma2(acc2[i][jp], a2, b2[jp]);
                }
            }
            if (t + 1 < NT) {
                const int nb = buf ^ 1;
                As[nb][aCol+0][aRow] = anext.x;
                As[nb][aCol+1][aRow] = anext.y;
                As[nb][aCol+2][aRow] = anext.z;
                As[nb][aCol+3][aRow] = anext.w;
                *(float4*)&Bs[nb][bRow][bCol] = bnext;
            }
            __syncthreads();
        }

        const int chunk = n0s >> 10;
        float* dst = (chunk == 0) ? g_Q : (chunk == 1) ? g_K : g_V;
        #pragma unroll
        for (int i = 0; i < 8; i++) {
            float r8[8];
            #pragma unroll
            for (int jp = 0; jp < 4; jp++) f2unpk(acc2[i][jp], r8[2*jp], r8[2*jp+1]);
            const int m  = m0s + aBase + ((i < 4) ? i : (28 + i));
            const int bb = m >> 11;
            const int l  = m & (LSEQ - 1);
            #pragma unroll
            for (int j4 = 0; j4 < 8; j4 += 4) {
                const int n = n0s + bBase + ((j4 == 0) ? 0 : 16);
                const int d = n - (chunk << 10);
                const int h = d >> 6;
                const int e = d & 63;
                float4 ov;
                ov.x = r8[j4+0] + bias[n+0];
                ov.y = r8[j4+1] + bias[n+1];
                ov.z = r8[j4+2] + bias[n+2];
                ov.w = r8[j4+3] + bias[n+3];
                *(float4*)&dst[((((size_t)bb*NH + h)*LSEQ + l) << 6) + e] = ov;
            }
        }
    }
}

// ---------------------------------------------------------------------------
// Kernel 2: fused causal flash attention, 128x128 CTA tile, 256 threads,
// 8x8 thread microtile — BYTE-IDENTICAL to the R12 passing version
// (measured best attn config: R13's 512-thread variant was -46us).
// ---------------------------------------------------------------------------
#define AT_SMEM 168960

__global__ __launch_bounds__(256) void attn_kernel(const float* __restrict__ Er)
{
    extern __shared__ float sm[];
    float* qT  = sm;               // [64][132]  qT[d][i]
    float* kT  = sm + 8448;        // [64][132]  kT[d][swz(j)]   (aliased by pS)
    float* erS = sm + 16896;       // [64][260]  erS[d][swz(mm)] (partly aliased)
    float* pS  = sm + 8448;        // [128][132] pS[i][j]  (row-major P)
    float* vS  = sm + 33536;       // [128][68]  vS[j][e]

    const int tid = threadIdx.x;
    const int tx  = tid & 15;
    const int ty  = tid >> 4;
    const int qt  = 15 - blockIdx.x;   // heavy tiles first
    const int bh  = blockIdx.y;
    const int i0  = qt << 7;

    const float* Qb = g_Q + (size_t)bh * LSEQ * HSIZE;
    const float* Kb = g_K + (size_t)bh * LSEQ * HSIZE;
    const float* Vb = g_V + (size_t)bh * LSEQ * HSIZE;

    #pragma unroll
    for (int r = 0; r < 8; r++) {
        int idx = tid + (r << 8);
        int row = idx >> 4;
        int f   = (idx & 15) << 2;
        float4 v = *(const float4*)(Qb + (size_t)(i0 + row) * HSIZE + f);
        qT[(f+0)*132 + row] = v.x;
        qT[(f+1)*132 + row] = v.y;
        qT[(f+2)*132 + row] = v.z;
        qT[(f+3)*132 + row] = v.w;
    }

    float mrow[8], lrow[8];
    uint64_t o2[8][2];
    #pragma unroll
    for (int a = 0; a < 8; a++) {
        mrow[a] = -INFINITY; lrow[a] = 0.f;
        o2[a][0] = 0ull; o2[a][1] = 0ull;
    }

    const int ec0 = 30 + ((tx - ty) << 1);

    for (int kt = 0; kt <= qt; kt++) {
        const int j0 = kt << 7;
        __syncthreads();

        #pragma unroll
        for (int r = 0; r < 8; r++) {
            int idx = tid + (r << 8);
            int row = idx >> 4;
            int f   = (idx & 15) << 2;
            float4 kv = *(const float4*)(Kb + (size_t)(j0 + row) * HSIZE + f);
            int c  = row >> 2;
            int cs = c ^ ((c >> 3) & 1);
            int colk = (cs << 2) | (row & 3);
            kT[(f+0)*132 + colk] = kv.x;
            kT[(f+1)*132 + colk] = kv.y;
            kT[(f+2)*132 + colk] = kv.z;
            kT[(f+3)*132 + colk] = kv.w;
            float4 vv = *(const float4*)(Vb + (size_t)(j0 + row) * HSIZE + f);
            *(float4*)&vS[row*68 + f] = vv;
        }
        const int m_lo = LSEQ - 128 - i0 + j0;
        #pragma unroll
        for (int r = 0; r < 16; r++) {
            int idx = tid + (r << 8);
            int mm  = idx >> 4;
            int f   = (idx & 15) << 2;
            int mg  = m_lo + mm;
            float4 ev = make_float4(0.f, 0.f, 0.f, 0.f);
            if (mg < LSEQ)
                ev = *(const float4*)(Er + (size_t)mg * HSIZE + f);
            int c  = mm >> 2;
            int cs = c ^ ((c >> 3) & 1);
            int cole = (cs << 2) | (mm & 3);
            erS[(f+0)*260 + cole] = ev.x;
            erS[(f+1)*260 + cole] = ev.y;
            erS[(f+2)*260 + cole] = ev.z;
            erS[(f+3)*260 + cole] = ev.w;
        }
        __syncthreads();

        uint64_t s2[8][4];
        #pragma unroll
        for (int a = 0; a < 8; a++)
            #pragma unroll
            for (int bp = 0; bp < 4; bp++) s2[a][bp] = 0ull;

        #pragma unroll 4
        for (int d = 0; d < 64; d++) {
            float q8[8], k8[8], er16[16];
            *(float4*)&q8[0] = *(const float4*)&qT[d*132 + (ty << 3)];
            *(float4*)&q8[4] = *(const float4*)&qT[d*132 + (ty << 3) + 4];
            {
                int c0 = tx << 1;
                int cs0 = c0 ^ ((c0 >> 3) & 1);
                int c1 = c0 + 1;
                int cs1 = c1 ^ ((c1 >> 3) & 1);
                *(float4*)&k8[0] = *(const float4*)&kT[d*132 + (cs0 << 2)];
                *(float4*)&k8[4] = *(const float4*)&kT[d*132 + (cs1 << 2)];
            }
            #pragma unroll
            for (int m = 0; m < 4; m++) {
                int c  = ec0 + m;
                int cs = c ^ ((c >> 3) & 1);
                *(float4*)&er16[m*4] = *(const float4*)&erS[d*260 + (cs << 2)];
            }
            uint64_t k2[4];
            #pragma unroll
            for (int bp = 0; bp < 4; bp++) k2[bp] = f2pk(k8[2*bp], k8[2*bp+1]);
            uint64_t EO[7], EE[7];
            #pragma unroll
            for (int s = 0; s < 7; s++) {
                EO[s] = f2pk(er16[2*s+1], er16[2*s+2]);
                EE[s] = f2pk(er16[2*s],   er16[2*s+1]);
            }
            #pragma unroll
            for (int a = 0; a < 8; a++) {
                const uint64_t q2 = f2pk(q8[a], q8[a]);
                const int a2 = a >> 1;
                if ((a & 1) == 0) {
                    #pragma unroll
                    for (int bp = 0; bp < 4; bp++)
                        ffma2(s2[a][bp], q2, fadd2(k2[bp], EO[3 + bp - a2]));
                } else {
                    #pragma unroll
                    for (int bp = 0; bp < 4; bp++)
                        ffma2(s2[a][bp], q2, fadd2(k2[bp], EE[3 + bp - a2]));
                }
            }
        }

        float s[8][8];
        #pragma unroll
        for (int a = 0; a < 8; a++)
            #pragma unroll
            for (int bp = 0; bp < 4; bp++)
                f2unpk(s2[a][bp], s[a][2*bp], s[a][2*bp+1]);

        const bool diag = (kt == qt);
        #pragma unroll
        for (int a = 0; a < 8; a++)
            #pragma unroll
            for (int b = 0; b < 8; b++) {
                float sv = s[a][b] * 0.125f;
                if (diag && ((tx << 3) + b) > ((ty << 3) + a)) sv = -INFINITY;
                s[a][b] = sv;
            }

        #pragma unroll
        for (int a = 0; a < 8; a++) {
            float mt = s[a][0];
            #pragma unroll
            for (int b = 1; b < 8; b++) mt = fmaxf(mt, s[a][b]);
            #pragma unroll
            for (int off = 8; off; off >>= 1)
                mt = fmaxf(mt, __shfl_xor_sync(0xffffffffu, mt, off));
            float mnew  = fmaxf(mrow[a], mt);
            float alpha = __expf(mrow[a] - mnew);
            mrow[a] = mnew;
            float ps = 0.f;
            #pragma unroll
            for (int b = 0; b < 8; b++) {
                float p = __expf(s[a][b] - mnew);
                s[a][b] = p;
                ps += p;
            }
            #pragma unroll
            for (int off = 8; off; off >>= 1)
                ps += __shfl_xor_sync(0xffffffffu, ps, off);
            lrow[a] = lrow[a] * alpha + ps;
            const uint64_t al2 = f2pk(alpha, alpha);
            o2[a][0] = fmul2(o2[a][0], al2);
            o2[a][1] = fmul2(o2[a][1], al2);
        }

        __syncthreads();
        #pragma unroll
        for (int a = 0; a < 8; a++) {
            *(float4*)&pS[((ty << 3) + a)*132 + (tx << 3)]     =
                make_float4(s[a][0], s[a][1], s[a][2], s[a][3]);
            *(float4*)&pS[((ty << 3) + a)*132 + (tx << 3) + 4] =
                make_float4(s[a][4], s[a][5], s[a][6], s[a][7]);
        }
        __syncthreads();

        #pragma unroll 2
        for (int jb = 0; jb < 128; jb += 4) {
            float4 pa[8];
            #pragma unroll
            for (int a = 0; a < 8; a++)
                pa[a] = *(const float4*)&pS[((ty << 3) + a)*132 + jb];
            float4 vv[4];
            #pragma unroll
            for (int jj = 0; jj < 4; jj++)
                vv[jj] = *(const float4*)&vS[(jb + jj)*68 + (tx << 2)];
            uint64_t v2[4][2];
            #pragma unroll
            for (int jj = 0; jj < 4; jj++) {
                v2[jj][0] = f2pk(vv[jj].x, vv[jj].y);
                v2[jj][1] = f2pk(vv[jj].z, vv[jj].w);
            }
            #pragma unroll
            for (int a = 0; a < 8; a++) {
                float pr[4] = {pa[a].x, pa[a].y, pa[a].z, pa[a].w};
                #pragma unroll
                for (int jj = 0; jj < 4; jj++) {
                    const uint64_t p2 = f2pk(pr[jj], pr[jj]);
                    ffma2(o2[a][0], p2, v2[jj][0]);
                    ffma2(o2[a][1], p2, v2[jj][1]);
                }
            }
        }
    }

    const int bb = bh >> 4;
    const int h  = bh & 15;
    #pragma unroll
    for (int a = 0; a < 8; a++) {
        float inv = 1.f / lrow[a];
        float o0, o1, o2v, o3;
        f2unpk(o2[a][0], o0, o1);
        f2unpk(o2[a][1], o2v, o3);
        int row = i0 + (ty << 3) + a;
        float4 ov = make_float4(o0*inv, o1*inv, o2v*inv, o3*inv);
        *(float4*)&g_Y[((size_t)bb*LSEQ + row)*DMODEL + (h << 6) + (tx << 2)] = ov;
    }
}

// ---------------------------------------------------------------------------
// Kernel 3: out = g_Y @ W_proj + b_proj.  PERSISTENT: 256 CTAs x 2 tiles
// (512 total, perfectly balanced vs 1.73 ragged waves before).
// ---------------------------------------------------------------------------
__global__ __launch_bounds__(256, 2) void gemm_proj_kernel(
    const float* __restrict__ W, const float* __restrict__ bias,
    float* __restrict__ out)
{
    __shared__ float As[2][8][128];
    __shared__ float Bs[2][8][128];
    const int tid  = threadIdx.x;
    const int wid  = tid >> 5;
    const int lane = tid & 31;
    const int wm   = wid >> 2;
    const int wn   = wid & 3;
    const int lr   = lane >> 2;
    const int lc   = lane & 3;
    const int aBase = wm*64 + lr*4;
    const int bBase = wn*32 + lc*4;

    const int aRow = tid >> 1;
    const int aCol = (tid & 1) << 2;
    const int bRow = tid >> 5;
    const int bCol = (tid & 31) << 2;

    for (int tile = blockIdx.x; tile < 512; tile += 256) {
        const int m0 = (tile >> 3) * 128;
        const int n0 = (tile & 7) * 128;

        const float* Ap = g_Y + (size_t)(m0 + aRow) * DMODEL + aCol;
        const float* Bp = W + (size_t)bRow * DMODEL + n0 + bCol;

        uint64_t acc2[8][4];
        #pragma unroll
        for (int i = 0; i < 8; i++)
            #pragma unroll
            for (int jp = 0; jp < 4; jp++) acc2[i][jp] = 0ull;

        __syncthreads();
        {
            float4 av = *(const float4*)(Ap);
            float4 bv = *(const float4*)(Bp);
            As[0][aCol+0][aRow] = av.x;
            As[0][aCol+1][aRow] = av.y;
            As[0][aCol+2][aRow] = av.z;
            As[0][aCol+3][aRow] = av.w;
            *(float4*)&Bs[0][bRow][bCol] = bv;
        }
        __syncthreads();

        const int NT = DMODEL / 8;
        for (int t = 0; t < NT; t++) {
            const int buf = t & 1;
            float4 anext, bnext;
            if (t + 1 < NT) {
                anext = *(const float4*)(Ap + (t+1)*8);
                bnext = *(const float4*)(Bp + (size_t)(t+1)*8*DMODEL);
            }
            #pragma unroll
            for (int kk = 0; kk < 8; kk++) {
                float a[8], b[8];
                *(float4*)&a[0] = *(const float4*)&As[buf][kk][aBase];
                *(float4*)&a[4] = *(const float4*)&As[buf][kk][aBase + 32];
                *(float4*)&b[0] = *(const float4*)&Bs[buf][kk][bBase];
                *(float4*)&b[4] = *(const float4*)&Bs[buf][kk][bBase + 16];
                uint64_t b2[4];
                #pragma unroll
                for (int jp = 0; jp < 4; jp++) b2[jp] = f2pk(b[2*jp], b[2*jp+1]);
                #pragma unroll
                for (int i = 0; i < 8; i++) {
                    const uint64_t a2 = f2pk(a[i], a[i]);
                    #pragma unroll
                    for (int jp = 0; jp < 4; jp++)
                        ffma2(acc2[i][jp], a2, b2[jp]);
                }
            }
            if (t + 1 < NT) {
                const int nb = buf ^ 1;
                As[nb][aCol+0][aRow] = anext.x;
                As[nb][aCol+1][aRow] = anext.y;
                As[nb][aCol+2][aRow] = anext.z;
                As[nb][aCol+3][aRow] = anext.w;
                *(float4*)&Bs[nb][bRow][bCol] = bnext;
            }
            __syncthreads();
        }

        #pragma unroll
        for (int i = 0; i < 8; i++) {
            float r8[8];
            #pragma unroll
            for (int jp = 0; jp < 4; jp++) f2unpk(acc2[i][jp], r8[2*jp], r8[2*jp+1]);
            const int m = m0 + aBase + ((i < 4) ? i : (28 + i));
            #pragma unroll
            for (int j4 = 0; j4 < 8; j4 += 4) {
                const int n = n0 + bBase + ((j4 == 0) ? 0 : 16);
                float4 ov;
                ov.x = r8[j4+0] + bias[n+0];
                ov.y = r8[j4+1] + bias[n+1];
                ov.z = r8[j4+2] + bias[n+2];
                ov.w = r8[j4+3] + bias[n+3];
                *(float4*)&out[(size_t)m * DMODEL + n] = ov;
            }
        }
    }
}

// ---------------------------------------------------------------------------
extern "C" void kernel_launch(void* const* d_in, const int* in_sizes, int n_in,
                              void* d_out, int out_size)
{
    const float* x      = (const float*)d_in[0];
    const float* W_attn = (const float*)d_in[1];
    const float* b_attn = (const float*)d_in[2];
    const float* W_proj = (const float*)d_in[3];
    const float* b_proj = (const float*)d_in[4];
    const float* Er     = (const float*)d_in[5];
    float* out = (float*)d_out;

    (void)in_sizes; (void)n_in; (void)out_size;

    cudaFuncSetAttribute(attn_kernel,
                         cudaFuncAttributeMaxDynamicSharedMemorySize, AT_SMEM);

    gemm_qkv_kernel<<<256, 256>>>(x, W_attn, b_attn);
    attn_kernel<<<dim3(16, 64), 256, AT_SMEM>>>(Er);
    gemm_proj_kernel<<<256, 256>>>(W_proj, b_proj, out);
}

// round 15
// speedup vs baseline: 1.8497x; 1.8497x over previous
#include <cuda_runtime.h>
#include <math.h>
#include <cstdint>

#define LSEQ   2048
#define NB     4
#define DMODEL 1024
#define NH     16
#define HSIZE  64
#define MROWS  (NB*LSEQ)   // 8192

// Scratch (allocation-free rule: __device__ globals)
__device__ float g_Q[(size_t)NB*NH*LSEQ*HSIZE];
__device__ float g_K[(size_t)NB*NH*LSEQ*HSIZE];
__device__ float g_V[(size_t)NB*NH*LSEQ*HSIZE];
__device__ float g_Y[(size_t)MROWS*DMODEL];

// ---------------------------------------------------------------------------
// Packed fp32x2 helpers (Blackwell family-level PTX, compute_103-safe)
// ---------------------------------------------------------------------------
__device__ __forceinline__ uint64_t f2pk(float lo, float hi) {
    uint64_t r;
    asm("mov.b64 %0, {%1, %2};"
        : "=l"(r) : "r"(__float_as_uint(lo)), "r"(__float_as_uint(hi)));
    return r;
}
__device__ __forceinline__ void f2unpk(uint64_t v, float& lo, float& hi) {
    uint32_t a, b;
    asm("mov.b64 {%0, %1}, %2;" : "=r"(a), "=r"(b) : "l"(v));
    lo = __uint_as_float(a);
    hi = __uint_as_float(b);
}
__device__ __forceinline__ void ffma2(uint64_t& d, uint64_t a, uint64_t b) {
    asm("fma.rn.f32x2 %0, %1, %2, %0;" : "+l"(d) : "l"(a), "l"(b));
}
__device__ __forceinline__ uint64_t fadd2(uint64_t a, uint64_t b) {
    uint64_t r;
    asm("add.rn.f32x2 %0, %1, %2;" : "=l"(r) : "l"(a), "l"(b));
    return r;
}
__device__ __forceinline__ uint64_t fmul2(uint64_t a, uint64_t b) {
    uint64_t r;
    asm("mul.rn.f32x2 %0, %1, %2;" : "=l"(r) : "l"(a), "l"(b));
    return r;
}

// ---------------------------------------------------------------------------
// Kernel 1: qkv = x @ W_attn + b_attn (identical to R12 passing version)
// quad layout + f32x2, double-buffered.
// ---------------------------------------------------------------------------
__global__ __launch_bounds__(256, 2) void gemm_qkv_kernel(
    const float* __restrict__ X, const float* __restrict__ W,
    const float* __restrict__ bias)
{
    __shared__ float As[2][8][128];
    __shared__ float Bs[2][8][128];
    const int tid  = threadIdx.x;
    const int wid  = tid >> 5;
    const int lane = tid & 31;
    const int wm   = wid >> 2;
    const int wn   = wid & 3;
    const int lr   = lane >> 2;
    const int lc   = lane & 3;
    const int m0   = blockIdx.y * 128;
    const int n0   = blockIdx.x * 128;
    const int aBase = wm*64 + lr*4;
    const int bBase = wn*32 + lc*4;

    const int aRow = tid >> 1;
    const int aCol = (tid & 1) << 2;
    const int bRow = tid >> 5;
    const int bCol = (tid & 31) << 2;

    const float* Ap = X + (size_t)(m0 + aRow) * DMODEL + aCol;
    const float* Bp = W + (size_t)bRow * 3072 + n0 + bCol;

    uint64_t acc2[8][4];
    #pragma unroll
    for (int i = 0; i < 8; i++)
        #pragma unroll
        for (int jp = 0; jp < 4; jp++) acc2[i][jp] = 0ull;

    {
        float4 av = *(const float4*)(Ap);
        float4 bv = *(const float4*)(Bp);
        As[0][aCol+0][aRow] = av.x;
        As[0][aCol+1][aRow] = av.y;
        As[0][aCol+2][aRow] = av.z;
        As[0][aCol+3][aRow] = av.w;
        *(float4*)&Bs[0][bRow][bCol] = bv;
    }
    __syncthreads();

    const int NT = DMODEL / 8;
    for (int t = 0; t < NT; t++) {
        const int buf = t & 1;
        float4 anext, bnext;
        if (t + 1 < NT) {
            anext = *(const float4*)(Ap + (t+1)*8);
            bnext = *(const float4*)(Bp + (size_t)(t+1)*8*3072);
        }
        #pragma unroll
        for (int kk = 0; kk < 8; kk++) {
            float a[8], b[8];
            *(float4*)&a[0] = *(const float4*)&As[buf][kk][aBase];
            *(float4*)&a[4] = *(const float4*)&As[buf][kk][aBase + 32];
            *(float4*)&b[0] = *(const float4*)&Bs[buf][kk][bBase];
            *(float4*)&b[4] = *(const float4*)&Bs[buf][kk][bBase + 16];
            uint64_t b2[4];
            #pragma unroll
            for (int jp = 0; jp < 4; jp++) b2[jp] = f2pk(b[2*jp], b[2*jp+1]);
            #pragma unroll
            for (int i = 0; i < 8; i++) {
                const uint64_t a2 = f2pk(a[i], a[i]);
                #pragma unroll
                for (int jp = 0; jp < 4; jp++)
                    ffma2(acc2[i][jp], a2, b2[jp]);
            }
        }
        if (t + 1 < NT) {
            const int nb = buf ^ 1;
            As[nb][aCol+0][aRow] = anext.x;
            As[nb][aCol+1][aRow] = anext.y;
            As[nb][aCol+2][aRow] = anext.z;
            As[nb][aCol+3][aRow] = anext.w;
            *(float4*)&Bs[nb][bRow][bCol] = bnext;
        }
        __syncthreads();
    }

    const int chunk = n0 >> 10;
    float* dst = (chunk == 0) ? g_Q : (chunk == 1) ? g_K : g_V;
    #pragma unroll
    for (int i = 0; i < 8; i++) {
        float r8[8];
        #pragma unroll
        for (int jp = 0; jp < 4; jp++) f2unpk(acc2[i][jp], r8[2*jp], r8[2*jp+1]);
        const int m  = m0 + aBase + ((i < 4) ? i : (28 + i));
        const int bb = m >> 11;
        const int l  = m & (LSEQ - 1);
        #pragma unroll
        for (int j4 = 0; j4 < 8; j4 += 4) {
            const int n = n0 + bBase + ((j4 == 0) ? 0 : 16);
            const int d = n - (chunk << 10);
            const int h = d >> 6;
            const int e = d & 63;
            float4 ov;
            ov.x = r8[j4+0] + bias[n+0];
            ov.y = r8[j4+1] + bias[n+1];
            ov.z = r8[j4+2] + bias[n+2];
            ov.w = r8[j4+3] + bias[n+3];
            *(float4*)&dst[((((size_t)bb*NH + h)*LSEQ + l) << 6) + e] = ov;
        }
    }
}

// ---------------------------------------------------------------------------
// Kernel 2: fused causal flash attention, 128x128 CTA tile, 256 threads,
// 8x8 thread microtile (R12 body).  GRID REORDERED: x = bh (64), y = qt
// index (16, heavy-first) so launch order is globally cost-monotone (LPT):
// all 16-iteration tiles first, all 1-iteration tiles last.
// ---------------------------------------------------------------------------
#define AT_SMEM 168960

__global__ __launch_bounds__(256) void attn_kernel(const float* __restrict__ Er)
{
    extern __shared__ float sm[];
    float* qT  = sm;               // [64][132]  qT[d][i]
    float* kT  = sm + 8448;        // [64][132]  kT[d][swz(j)]   (aliased by pS)
    float* erS = sm + 16896;       // [64][260]  erS[d][swz(mm)] (partly aliased)
    float* pS  = sm + 8448;        // [128][132] pS[i][j]  (row-major P)
    float* vS  = sm + 33536;       // [128][68]  vS[j][e]

    const int tid = threadIdx.x;
    const int tx  = tid & 15;
    const int ty  = tid >> 4;
    const int bh  = blockIdx.x;        // 0..63
    const int qt  = 15 - blockIdx.y;   // heavy tiles launch first (y-major tail)
    const int i0  = qt << 7;

    const float* Qb = g_Q + (size_t)bh * LSEQ * HSIZE;
    const float* Kb = g_K + (size_t)bh * LSEQ * HSIZE;
    const float* Vb = g_V + (size_t)bh * LSEQ * HSIZE;

    #pragma unroll
    for (int r = 0; r < 8; r++) {
        int idx = tid + (r << 8);
        int row = idx >> 4;
        int f   = (idx & 15) << 2;
        float4 v = *(const float4*)(Qb + (size_t)(i0 + row) * HSIZE + f);
        qT[(f+0)*132 + row] = v.x;
        qT[(f+1)*132 + row] = v.y;
        qT[(f+2)*132 + row] = v.z;
        qT[(f+3)*132 + row] = v.w;
    }

    float mrow[8], lrow[8];
    uint64_t o2[8][2];
    #pragma unroll
    for (int a = 0; a < 8; a++) {
        mrow[a] = -INFINITY; lrow[a] = 0.f;
        o2[a][0] = 0ull; o2[a][1] = 0ull;
    }

    const int ec0 = 30 + ((tx - ty) << 1);

    for (int kt = 0; kt <= qt; kt++) {
        const int j0 = kt << 7;
        __syncthreads();

        #pragma unroll
        for (int r = 0; r < 8; r++) {
            int idx = tid + (r << 8);
            int row = idx >> 4;
            int f   = (idx & 15) << 2;
            float4 kv = *(const float4*)(Kb + (size_t)(j0 + row) * HSIZE + f);
            int c  = row >> 2;
            int cs = c ^ ((c >> 3) & 1);
            int colk = (cs << 2) | (row & 3);
            kT[(f+0)*132 + colk] = kv.x;
            kT[(f+1)*132 + colk] = kv.y;
            kT[(f+2)*132 + colk] = kv.z;
            kT[(f+3)*132 + colk] = kv.w;
            float4 vv = *(const float4*)(Vb + (size_t)(j0 + row) * HSIZE + f);
            *(float4*)&vS[row*68 + f] = vv;
        }
        const int m_lo = LSEQ - 128 - i0 + j0;
        #pragma unroll
        for (int r = 0; r < 16; r++) {
            int idx = tid + (r << 8);
            int mm  = idx >> 4;
            int f   = (idx & 15) << 2;
            int mg  = m_lo + mm;
            float4 ev = make_float4(0.f, 0.f, 0.f, 0.f);
            if (mg < LSEQ)
                ev = *(const float4*)(Er + (size_t)mg * HSIZE + f);
            int c  = mm >> 2;
            int cs = c ^ ((c >> 3) & 1);
            int cole = (cs << 2) | (mm & 3);
            erS[(f+0)*260 + cole] = ev.x;
            erS[(f+1)*260 + cole] = ev.y;
            erS[(f+2)*260 + cole] = ev.z;
            erS[(f+3)*260 + cole] = ev.w;
        }
        __syncthreads();

        uint64_t s2[8][4];
        #pragma unroll
        for (int a = 0; a < 8; a++)
            #pragma unroll
            for (int bp = 0; bp < 4; bp++) s2[a][bp] = 0ull;

        #pragma unroll 4
        for (int d = 0; d < 64; d++) {
            float q8[8], k8[8], er16[16];
            *(float4*)&q8[0] = *(const float4*)&qT[d*132 + (ty << 3)];
            *(float4*)&q8[4] = *(const float4*)&qT[d*132 + (ty << 3) + 4];
            {
                int c0 = tx << 1;
                int cs0 = c0 ^ ((c0 >> 3) & 1);
                int c1 = c0 + 1;
                int cs1 = c1 ^ ((c1 >> 3) & 1);
                *(float4*)&k8[0] = *(const float4*)&kT[d*132 + (cs0 << 2)];
                *(float4*)&k8[4] = *(const float4*)&kT[d*132 + (cs1 << 2)];
            }
            #pragma unroll
            for (int m = 0; m < 4; m++) {
                int c  = ec0 + m;
                int cs = c ^ ((c >> 3) & 1);
                *(float4*)&er16[m*4] = *(const float4*)&erS[d*260 + (cs << 2)];
            }
            uint64_t k2[4];
            #pragma unroll
            for (int bp = 0; bp < 4; bp++) k2[bp] = f2pk(k8[2*bp], k8[2*bp+1]);
            uint64_t EO[7], EE[7];
            #pragma unroll
            for (int s = 0; s < 7; s++) {
                EO[s] = f2pk(er16[2*s+1], er16[2*s+2]);
                EE[s] = f2pk(er16[2*s],   er16[2*s+1]);
            }
            #pragma unroll
            for (int a = 0; a < 8; a++) {
                const uint64_t q2 = f2pk(q8[a], q8[a]);
                const int a2 = a >> 1;
                if ((a & 1) == 0) {
                    #pragma unroll
                    for (int bp = 0; bp < 4; bp++)
                        ffma2(s2[a][bp], q2, fadd2(k2[bp], EO[3 + bp - a2]));
                } else {
                    #pragma unroll
                    for (int bp = 0; bp < 4; bp++)
                        ffma2(s2[a][bp], q2, fadd2(k2[bp], EE[3 + bp - a2]));
                }
            }
        }

        float s[8][8];
        #pragma unroll
        for (int a = 0; a < 8; a++)
            #pragma unroll
            for (int bp = 0; bp < 4; bp++)
                f2unpk(s2[a][bp], s[a][2*bp], s[a][2*bp+1]);

        const bool diag = (kt == qt);
        #pragma unroll
        for (int a = 0; a < 8; a++)
            #pragma unroll
            for (int b = 0; b < 8; b++) {
                float sv = s[a][b] * 0.125f;
                if (diag && ((tx << 3) + b) > ((ty << 3) + a)) sv = -INFINITY;
                s[a][b] = sv;
            }

        #pragma unroll
        for (int a = 0; a < 8; a++) {
            float mt = s[a][0];
            #pragma unroll
            for (int b = 1; b < 8; b++) mt = fmaxf(mt, s[a][b]);
            #pragma unroll
            for (int off = 8; off; off >>= 1)
                mt = fmaxf(mt, __shfl_xor_sync(0xffffffffu, mt, off));
            float mnew  = fmaxf(mrow[a], mt);
            float alpha = __expf(mrow[a] - mnew);
            mrow[a] = mnew;
            float ps = 0.f;
            #pragma unroll
            for (int b = 0; b < 8; b++) {
                float p = __expf(s[a][b] - mnew);
                s[a][b] = p;
                ps += p;
            }
            #pragma unroll
            for (int off = 8; off; off >>= 1)
                ps += __shfl_xor_sync(0xffffffffu, ps, off);
            lrow[a] = lrow[a] * alpha + ps;
            const uint64_t al2 = f2pk(alpha, alpha);
            o2[a][0] = fmul2(o2[a][0], al2);
            o2[a][1] = fmul2(o2[a][1], al2);
        }

        __syncthreads();
        #pragma unroll
        for (int a = 0; a < 8; a++) {
            *(float4*)&pS[((ty << 3) + a)*132 + (tx << 3)]     =
                make_float4(s[a][0], s[a][1], s[a][2], s[a][3]);
            *(float4*)&pS[((ty << 3) + a)*132 + (tx << 3) + 4] =
                make_float4(s[a][4], s[a][5], s[a][6], s[a][7]);
        }
        __syncthreads();

        #pragma unroll 2
        for (int jb = 0; jb < 128; jb += 4) {
            float4 pa[8];
            #pragma unroll
            for (int a = 0; a < 8; a++)
                pa[a] = *(const float4*)&pS[((ty << 3) + a)*132 + jb];
            float4 vv[4];
            #pragma unroll
            for (int jj = 0; jj < 4; jj++)
                vv[jj] = *(const float4*)&vS[(jb + jj)*68 + (tx << 2)];
            uint64_t v2[4][2];
            #pragma unroll
            for (int jj = 0; jj < 4; jj++) {
                v2[jj][0] = f2pk(vv[jj].x, vv[jj].y);
                v2[jj][1] = f2pk(vv[jj].z, vv[jj].w);
            }
            #pragma unroll
            for (int a = 0; a < 8; a++) {
                float pr[4] = {pa[a].x, pa[a].y, pa[a].z, pa[a].w};
                #pragma unroll
                for (int jj = 0; jj < 4; jj++) {
                    const uint64_t p2 = f2pk(pr[jj], pr[jj]);
                    ffma2(o2[a][0], p2, v2[jj][0]);
                    ffma2(o2[a][1], p2, v2[jj][1]);
                }
            }
        }
    }

    const int bb = bh >> 4;
    const int h  = bh & 15;
    #pragma unroll
    for (int a = 0; a < 8; a++) {
        float inv = 1.f / lrow[a];
        float o0, o1, o2v, o3;
        f2unpk(o2[a][0], o0, o1);
        f2unpk(o2[a][1], o2v, o3);
        int row = i0 + (ty << 3) + a;
        float4 ov = make_float4(o0*inv, o1*inv, o2v*inv, o3*inv);
        *(float4*)&g_Y[((size_t)bb*LSEQ + row)*DMODEL + (h << 6) + (tx << 2)] = ov;
    }
}

// ---------------------------------------------------------------------------
// Kernel 3: out = g_Y @ W_proj + b_proj (identical to R12 passing version)
// ---------------------------------------------------------------------------
__global__ __launch_bounds__(256, 2) void gemm_proj_kernel(
    const float* __restrict__ W, const float* __restrict__ bias,
    float* __restrict__ out)
{
    __shared__ float As[2][8][128];
    __shared__ float Bs[2][8][128];
    const int tid  = threadIdx.x;
    const int wid  = tid >> 5;
    const int lane = tid & 31;
    const int wm   = wid >> 2;
    const int wn   = wid & 3;
    const int lr   = lane >> 2;
    const int lc   = lane & 3;
    const int m0   = blockIdx.y * 128;
    const int n0   = blockIdx.x * 128;
    const int aBase = wm*64 + lr*4;
    const int bBase = wn*32 + lc*4;

    const int aRow = tid >> 1;
    const int aCol = (tid & 1) << 2;
    const int bRow = tid >> 5;
    const int bCol = (tid & 31) << 2;

    const float* Ap = g_Y + (size_t)(m0 + aRow) * DMODEL + aCol;
    const float* Bp = W + (size_t)bRow * DMODEL + n0 + bCol;

    uint64_t acc2[8][4];
    #pragma unroll
    for (int i = 0; i < 8; i++)
        #pragma unroll
        for (int jp = 0; jp < 4; jp++) acc2[i][jp] = 0ull;

    {
        float4 av = *(const float4*)(Ap);
        float4 bv = *(const float4*)(Bp);
        As[0][aCol+0][aRow] = av.x;
        As[0][aCol+1][aRow] = av.y;
        As[0][aCol+2][aRow] = av.z;
        As[0][aCol+3][aRow] = av.w;
        *(float4*)&Bs[0][bRow][bCol] = bv;
    }
    __syncthreads();

    const int NT = DMODEL / 8;
    for (int t = 0; t < NT; t++) {
        const int buf = t & 1;
        float4 anext, bnext;
        if (t + 1 < NT) {
            anext = *(const float4*)(Ap + (t+1)*8);
            bnext = *(const float4*)(Bp + (size_t)(t+1)*8*DMODEL);
        }
        #pragma unroll
        for (int kk = 0; kk < 8; kk++) {
            float a[8], b[8];
            *(float4*)&a[0] = *(const float4*)&As[buf][kk][aBase];
            *(float4*)&a[4] = *(const float4*)&As[buf][kk][aBase + 32];
            *(float4*)&b[0] = *(const float4*)&Bs[buf][kk][bBase];
            *(float4*)&b[4] = *(const float4*)&Bs[buf][kk][bBase + 16];
            uint64_t b2[4];
            #pragma unroll
            for (int jp = 0; jp < 4; jp++) b2[jp] = f2pk(b[2*jp], b[2*jp+1]);
            #pragma unroll
            for (int i = 0; i < 8; i++) {
                const uint64_t a2 = f2pk(a[i], a[i]);
                #pragma unroll
                for (int jp = 0; jp < 4; jp++)
                    ffma2(acc2[i][jp], a2, b2[jp]);
            }
        }
        if (t + 1 < NT) {
            const int nb = buf ^ 1;
            As[nb][aCol+0][aRow] = anext.x;
            As[nb][aCol+1][aRow] = anext.y;
            As[nb][aCol+2][aRow] = anext.z;
            As[nb][aCol+3][aRow] = anext.w;
            *(float4*)&Bs[nb][bRow][bCol] = bnext;
        }
        __syncthreads();
    }

    #pragma unroll
    for (int i = 0; i < 8; i++) {
        float r8[8];
        #pragma unroll
        for (int jp = 0; jp < 4; jp++) f2unpk(acc2[i][jp], r8[2*jp], r8[2*jp+1]);
        const int m = m0 + aBase + ((i < 4) ? i : (28 + i));
        #pragma unroll
        for (int j4 = 0; j4 < 8; j4 += 4) {
            const int n = n0 + bBase + ((j4 == 0) ? 0 : 16);
            float4 ov;
            ov.x = r8[j4+0] + bias[n+0];
            ov.y = r8[j4+1] + bias[n+1];
            ov.z = r8[j4+2] + bias[n+2];
            ov.w = r8[j4+3] + bias[n+3];
            *(float4*)&out[(size_t)m * DMODEL + n] = ov;
        }
    }
}

// ---------------------------------------------------------------------------
extern "C" void kernel_launch(void* const* d_in, const int* in_sizes, int n_in,
                              void* d_out, int out_size)
{
    const float* x      = (const float*)d_in[0];
    const float* W_attn = (const float*)d_in[1];
    const float* b_attn = (const float*)d_in[2];
    const float* W_proj = (const float*)d_in[3];
    const float* b_proj = (const float*)d_in[4];
    const float* Er     = (const float*)d_in[5];
    float* out = (float*)d_out;

    (void)in_sizes; (void)n_in; (void)out_size;

    cudaFuncSetAttribute(attn_kernel,
                         cudaFuncAttributeMaxDynamicSharedMemorySize, AT_SMEM);

    gemm_qkv_kernel<<<dim3(24, 64), 256>>>(x, W_attn, b_attn);
    attn_kernel<<<dim3(64, 16), 256, AT_SMEM>>>(Er);
    gemm_proj_kernel<<<dim3(8, 64), 256>>>(W_proj, b_proj, out);
}

// round 16
// speedup vs baseline: 1.9268x; 1.0417x over previous
#include <cuda_runtime.h>
#include <math.h>
#include <cstdint>

#define LSEQ   2048
#define NB     4
#define DMODEL 1024
#define NH     16
#define HSIZE  64
#define MROWS  (NB*LSEQ)   // 8192

// Scratch (allocation-free rule: __device__ globals)
__device__ float g_Q[(size_t)NB*NH*LSEQ*HSIZE];
__device__ float g_K[(size_t)NB*NH*LSEQ*HSIZE];
__device__ float g_V[(size_t)NB*NH*LSEQ*HSIZE];
__device__ float g_Y[(size_t)MROWS*DMODEL];

// ---------------------------------------------------------------------------
// Packed fp32x2 helpers (Blackwell family-level PTX, compute_103-safe)
// ---------------------------------------------------------------------------
__device__ __forceinline__ uint64_t f2pk(float lo, float hi) {
    uint64_t r;
    asm("mov.b64 %0, {%1, %2};"
        : "=l"(r) : "r"(__float_as_uint(lo)), "r"(__float_as_uint(hi)));
    return r;
}
__device__ __forceinline__ void f2unpk(uint64_t v, float& lo, float& hi) {
    uint32_t a, b;
    asm("mov.b64 {%0, %1}, %2;" : "=r"(a), "=r"(b) : "l"(v));
    lo = __uint_as_float(a);
    hi = __uint_as_float(b);
}
__device__ __forceinline__ void ffma2(uint64_t& d, uint64_t a, uint64_t b) {
    asm("fma.rn.f32x2 %0, %1, %2, %0;" : "+l"(d) : "l"(a), "l"(b));
}
__device__ __forceinline__ uint64_t fadd2(uint64_t a, uint64_t b) {
    uint64_t r;
    asm("add.rn.f32x2 %0, %1, %2;" : "=l"(r) : "l"(a), "l"(b));
    return r;
}
__device__ __forceinline__ uint64_t fmul2(uint64_t a, uint64_t b) {
    uint64_t r;
    asm("mul.rn.f32x2 %0, %1, %2;" : "=l"(r) : "l"(a), "l"(b));
    return r;
}

// ---------------------------------------------------------------------------
// Kernel 1: qkv = x @ W_attn + b_attn.  BK=16 (64 iters, half the barriers),
// quad fragment layout + f32x2, double-buffered smem.
// ---------------------------------------------------------------------------
__global__ __launch_bounds__(256, 2) void gemm_qkv_kernel(
    const float* __restrict__ X, const float* __restrict__ W,
    const float* __restrict__ bias)
{
    __shared__ float As[2][16][128];
    __shared__ float Bs[2][16][128];
    const int tid  = threadIdx.x;
    const int wid  = tid >> 5;
    const int lane = tid & 31;
    const int wm   = wid >> 2;
    const int wn   = wid & 3;
    const int lr   = lane >> 2;
    const int lc   = lane & 3;
    const int m0   = blockIdx.y * 128;
    const int n0   = blockIdx.x * 128;
    const int aBase = wm*64 + lr*4;
    const int bBase = wn*32 + lc*4;

    // A loader: 512 float4 chunks per stage (128 rows x 4 chunks), 2/thread
    // B loader: 512 float4 chunks per stage (16 rows x 32 chunks), 2/thread
    const int aRow0 = tid >> 1;                 // chunk0 row
    const int aCol0 = (tid & 1) << 3;           // 0 or 8 (float index)
    const int bRow0 = tid >> 5;                 // 0..7
    const int bCol0 = (tid & 31) << 2;

    const float* ApA = X + (size_t)(m0 + aRow0) * DMODEL + aCol0;
    const float* BpA = W + (size_t)bRow0 * 3072 + n0 + bCol0;
    const float* BpB = W + (size_t)(bRow0 + 8) * 3072 + n0 + bCol0;

    uint64_t acc2[8][4];
    #pragma unroll
    for (int i = 0; i < 8; i++)
        #pragma unroll
        for (int jp = 0; jp < 4; jp++) acc2[i][jp] = 0ull;

    // prologue: stage 0
    {
        float4 a0 = *(const float4*)(ApA);
        float4 a1 = *(const float4*)(ApA + 4);
        float4 b0 = *(const float4*)(BpA);
        float4 b1 = *(const float4*)(BpB);
        As[0][aCol0+0][aRow0] = a0.x;
        As[0][aCol0+1][aRow0] = a0.y;
        As[0][aCol0+2][aRow0] = a0.z;
        As[0][aCol0+3][aRow0] = a0.w;
        As[0][aCol0+4][aRow0] = a1.x;
        As[0][aCol0+5][aRow0] = a1.y;
        As[0][aCol0+6][aRow0] = a1.z;
        As[0][aCol0+7][aRow0] = a1.w;
        *(float4*)&Bs[0][bRow0][bCol0]     = b0;
        *(float4*)&Bs[0][bRow0 + 8][bCol0] = b1;
    }
    __syncthreads();

    const int NT = DMODEL / 16;   // 64
    for (int t = 0; t < NT; t++) {
        const int buf = t & 1;
        float4 a0n, a1n, b0n, b1n;
        if (t + 1 < NT) {
            const int k0 = (t + 1) * 16;
            a0n = *(const float4*)(ApA + k0);
            a1n = *(const float4*)(ApA + k0 + 4);
            b0n = *(const float4*)(BpA + (size_t)k0 * 3072);
            b1n = *(const float4*)(BpB + (size_t)k0 * 3072);
        }
        #pragma unroll
        for (int kk = 0; kk < 16; kk++) {
            float a[8], b[8];
            *(float4*)&a[0] = *(const float4*)&As[buf][kk][aBase];
            *(float4*)&a[4] = *(const float4*)&As[buf][kk][aBase + 32];
            *(float4*)&b[0] = *(const float4*)&Bs[buf][kk][bBase];
            *(float4*)&b[4] = *(const float4*)&Bs[buf][kk][bBase + 16];
            uint64_t b2[4];
            #pragma unroll
            for (int jp = 0; jp < 4; jp++) b2[jp] = f2pk(b[2*jp], b[2*jp+1]);
            #pragma unroll
            for (int i = 0; i < 8; i++) {
                const uint64_t a2 = f2pk(a[i], a[i]);
                #pragma unroll
                for (int jp = 0; jp < 4; jp++)
                    ffma2(acc2[i][jp], a2, b2[jp]);
            }
        }
        if (t + 1 < NT) {
            const int nb = buf ^ 1;
            As[nb][aCol0+0][aRow0] = a0n.x;
            As[nb][aCol0+1][aRow0] = a0n.y;
            As[nb][aCol0+2][aRow0] = a0n.z;
            As[nb][aCol0+3][aRow0] = a0n.w;
            As[nb][aCol0+4][aRow0] = a1n.x;
            As[nb][aCol0+5][aRow0] = a1n.y;
            As[nb][aCol0+6][aRow0] = a1n.z;
            As[nb][aCol0+7][aRow0] = a1n.w;
            *(float4*)&Bs[nb][bRow0][bCol0]     = b0n;
            *(float4*)&Bs[nb][bRow0 + 8][bCol0] = b1n;
        }
        __syncthreads();
    }

    const int chunk = n0 >> 10;
    float* dst = (chunk == 0) ? g_Q : (chunk == 1) ? g_K : g_V;
    #pragma unroll
    for (int i = 0; i < 8; i++) {
        float r8[8];
        #pragma unroll
        for (int jp = 0; jp < 4; jp++) f2unpk(acc2[i][jp], r8[2*jp], r8[2*jp+1]);
        const int m  = m0 + aBase + ((i < 4) ? i : (28 + i));
        const int bb = m >> 11;
        const int l  = m & (LSEQ - 1);
        #pragma unroll
        for (int j4 = 0; j4 < 8; j4 += 4) {
            const int n = n0 + bBase + ((j4 == 0) ? 0 : 16);
            const int d = n - (chunk << 10);
            const int h = d >> 6;
            const int e = d & 63;
            float4 ov;
            ov.x = r8[j4+0] + bias[n+0];
            ov.y = r8[j4+1] + bias[n+1];
            ov.z = r8[j4+2] + bias[n+2];
            ov.w = r8[j4+3] + bias[n+3];
            *(float4*)&dst[((((size_t)bb*NH + h)*LSEQ + l) << 6) + e] = ov;
        }
    }
}

// ---------------------------------------------------------------------------
// Kernel 2: fused causal flash attention — R15 champion body + LPT grid.
// Only change: 1/8 scale folded into qT at fill (removes mask-pass muls).
// ---------------------------------------------------------------------------
#define AT_SMEM 168960

__global__ __launch_bounds__(256) void attn_kernel(const float* __restrict__ Er)
{
    extern __shared__ float sm[];
    float* qT  = sm;               // [64][132]  qT[d][i]  (pre-scaled by 1/8)
    float* kT  = sm + 8448;        // [64][132]  kT[d][swz(j)]   (aliased by pS)
    float* erS = sm + 16896;       // [64][260]  erS[d][swz(mm)] (partly aliased)
    float* pS  = sm + 8448;        // [128][132] pS[i][j]
    float* vS  = sm + 33536;       // [128][68]  vS[j][e]

    const int tid = threadIdx.x;
    const int tx  = tid & 15;
    const int ty  = tid >> 4;
    const int bh  = blockIdx.x;        // 0..63
    const int qt  = 15 - blockIdx.y;   // heavy tiles launch first (LPT)
    const int i0  = qt << 7;

    const float* Qb = g_Q + (size_t)bh * LSEQ * HSIZE;
    const float* Kb = g_K + (size_t)bh * LSEQ * HSIZE;
    const float* Vb = g_V + (size_t)bh * LSEQ * HSIZE;

    #pragma unroll
    for (int r = 0; r < 8; r++) {
        int idx = tid + (r << 8);
        int row = idx >> 4;
        int f   = (idx & 15) << 2;
        float4 v = *(const float4*)(Qb + (size_t)(i0 + row) * HSIZE + f);
        qT[(f+0)*132 + row] = v.x * 0.125f;
        qT[(f+1)*132 + row] = v.y * 0.125f;
        qT[(f+2)*132 + row] = v.z * 0.125f;
        qT[(f+3)*132 + row] = v.w * 0.125f;
    }

    float mrow[8], lrow[8];
    uint64_t o2[8][2];
    #pragma unroll
    for (int a = 0; a < 8; a++) {
        mrow[a] = -INFINITY; lrow[a] = 0.f;
        o2[a][0] = 0ull; o2[a][1] = 0ull;
    }

    const int ec0 = 30 + ((tx - ty) << 1);

    for (int kt = 0; kt <= qt; kt++) {
        const int j0 = kt << 7;
        __syncthreads();

        #pragma unroll
        for (int r = 0; r < 8; r++) {
            int idx = tid + (r << 8);
            int row = idx >> 4;
            int f   = (idx & 15) << 2;
            float4 kv = *(const float4*)(Kb + (size_t)(j0 + row) * HSIZE + f);
            int c  = row >> 2;
            int cs = c ^ ((c >> 3) & 1);
            int colk = (cs << 2) | (row & 3);
            kT[(f+0)*132 + colk] = kv.x;
            kT[(f+1)*132 + colk] = kv.y;
            kT[(f+2)*132 + colk] = kv.z;
            kT[(f+3)*132 + colk] = kv.w;
            float4 vv = *(const float4*)(Vb + (size_t)(j0 + row) * HSIZE + f);
            *(float4*)&vS[row*68 + f] = vv;
        }
        const int m_lo = LSEQ - 128 - i0 + j0;
        #pragma unroll
        for (int r = 0; r < 16; r++) {
            int idx = tid + (r << 8);
            int mm  = idx >> 4;
            int f   = (idx & 15) << 2;
            int mg  = m_lo + mm;
            float4 ev = make_float4(0.f, 0.f, 0.f, 0.f);
            if (mg < LSEQ)
                ev = *(const float4*)(Er + (size_t)mg * HSIZE + f);
            int c  = mm >> 2;
            int cs = c ^ ((c >> 3) & 1);
            int cole = (cs << 2) | (mm & 3);
            erS[(f+0)*260 + cole] = ev.x;
            erS[(f+1)*260 + cole] = ev.y;
            erS[(f+2)*260 + cole] = ev.z;
            erS[(f+3)*260 + cole] = ev.w;
        }
        __syncthreads();

        uint64_t s2[8][4];
        #pragma unroll
        for (int a = 0; a < 8; a++)
            #pragma unroll
            for (int bp = 0; bp < 4; bp++) s2[a][bp] = 0ull;

        #pragma unroll 4
        for (int d = 0; d < 64; d++) {
            float q8[8], k8[8], er16[16];
            *(float4*)&q8[0] = *(const float4*)&qT[d*132 + (ty << 3)];
            *(float4*)&q8[4] = *(const float4*)&qT[d*132 + (ty << 3) + 4];
            {
                int c0 = tx << 1;
                int cs0 = c0 ^ ((c0 >> 3) & 1);
                int c1 = c0 + 1;
                int cs1 = c1 ^ ((c1 >> 3) & 1);
                *(float4*)&k8[0] = *(const float4*)&kT[d*132 + (cs0 << 2)];
                *(float4*)&k8[4] = *(const float4*)&kT[d*132 + (cs1 << 2)];
            }
            #pragma unroll
            for (int m = 0; m < 4; m++) {
                int c  = ec0 + m;
                int cs = c ^ ((c >> 3) & 1);
                *(float4*)&er16[m*4] = *(const float4*)&erS[d*260 + (cs << 2)];
            }
            uint64_t k2[4];
            #pragma unroll
            for (int bp = 0; bp < 4; bp++) k2[bp] = f2pk(k8[2*bp], k8[2*bp+1]);
            uint64_t EO[7], EE[7];
            #pragma unroll
            for (int s = 0; s < 7; s++) {
                EO[s] = f2pk(er16[2*s+1], er16[2*s+2]);
                EE[s] = f2pk(er16[2*s],   er16[2*s+1]);
            }
            #pragma unroll
            for (int a = 0; a < 8; a++) {
                const uint64_t q2 = f2pk(q8[a], q8[a]);
                const int a2 = a >> 1;
                if ((a & 1) == 0) {
                    #pragma unroll
                    for (int bp = 0; bp < 4; bp++)
                        ffma2(s2[a][bp], q2, fadd2(k2[bp], EO[3 + bp - a2]));
                } else {
                    #pragma unroll
                    for (int bp = 0; bp < 4; bp++)
                        ffma2(s2[a][bp], q2, fadd2(k2[bp], EE[3 + bp - a2]));
                }
            }
        }

        float s[8][8];
        #pragma unroll
        for (int a = 0; a < 8; a++)
            #pragma unroll
            for (int bp = 0; bp < 4; bp++)
                f2unpk(s2[a][bp], s[a][2*bp], s[a][2*bp+1]);

        const bool diag = (kt == qt);
        if (diag) {
            #pragma unroll
            for (int a = 0; a < 8; a++)
                #pragma unroll
                for (int b = 0; b < 8; b++)
                    if (((tx << 3) + b) > ((ty << 3) + a)) s[a][b] = -INFINITY;
        }

        #pragma unroll
        for (int a = 0; a < 8; a++) {
            float mt = s[a][0];
            #pragma unroll
            for (int b = 1; b < 8; b++) mt = fmaxf(mt, s[a][b]);
            #pragma unroll
            for (int off = 8; off; off >>= 1)
                mt = fmaxf(mt, __shfl_xor_sync(0xffffffffu, mt, off));
            float mnew  = fmaxf(mrow[a], mt);
            float alpha = __expf(mrow[a] - mnew);
            mrow[a] = mnew;
            float ps = 0.f;
            #pragma unroll
            for (int b = 0; b < 8; b++) {
                float p = __expf(s[a][b] - mnew);
                s[a][b] = p;
                ps += p;
            }
            #pragma unroll
            for (int off = 8; off; off >>= 1)
                ps += __shfl_xor_sync(0xffffffffu, ps, off);
            lrow[a] = lrow[a] * alpha + ps;
            const uint64_t al2 = f2pk(alpha, alpha);
            o2[a][0] = fmul2(o2[a][0], al2);
            o2[a][1] = fmul2(o2[a][1], al2);
        }

        __syncthreads();
        #pragma unroll
        for (int a = 0; a < 8; a++) {
            *(float4*)&pS[((ty << 3) + a)*132 + (tx << 3)]     =
                make_float4(s[a][0], s[a][1], s[a][2], s[a][3]);
            *(float4*)&pS[((ty << 3) + a)*132 + (tx << 3) + 4] =
                make_float4(s[a][4], s[a][5], s[a][6], s[a][7]);
        }
        __syncthreads();

        #pragma unroll 2
        for (int jb = 0; jb < 128; jb += 4) {
            float4 pa[8];
            #pragma unroll
            for (int a = 0; a < 8; a++)
                pa[a] = *(const float4*)&pS[((ty << 3) + a)*132 + jb];
            float4 vv[4];
            #pragma unroll
            for (int jj = 0; jj < 4; jj++)
                vv[jj] = *(const float4*)&vS[(jb + jj)*68 + (tx << 2)];
            uint64_t v2[4][2];
            #pragma unroll
            for (int jj = 0; jj < 4; jj++) {
                v2[jj][0] = f2pk(vv[jj].x, vv[jj].y);
                v2[jj][1] = f2pk(vv[jj].z, vv[jj].w);
            }
            #pragma unroll
            for (int a = 0; a < 8; a++) {
                float pr[4] = {pa[a].x, pa[a].y, pa[a].z, pa[a].w};
                #pragma unroll
                for (int jj = 0; jj < 4; jj++) {
                    const uint64_t p2 = f2pk(pr[jj], pr[jj]);
                    ffma2(o2[a][0], p2, v2[jj][0]);
                    ffma2(o2[a][1], p2, v2[jj][1]);
                }
            }
        }
    }

    const int bb = bh >> 4;
    const int h  = bh & 15;
    #pragma unroll
    for (int a = 0; a < 8; a++) {
        float inv = 1.f / lrow[a];
        float o0, o1, o2v, o3;
        f2unpk(o2[a][0], o0, o1);
        f2unpk(o2[a][1], o2v, o3);
        int row = i0 + (ty << 3) + a;
        float4 ov = make_float4(o0*inv, o1*inv, o2v*inv, o3*inv);
        *(float4*)&g_Y[((size_t)bb*LSEQ + row)*DMODEL + (h << 6) + (tx << 2)] = ov;
    }
}

// ---------------------------------------------------------------------------
// Kernel 3: out = g_Y @ W_proj + b_proj.  BK=16 like kernel 1.
// ---------------------------------------------------------------------------
__global__ __launch_bounds__(256, 2) void gemm_proj_kernel(
    const float* __restrict__ W, const float* __restrict__ bias,
    float* __restrict__ out)
{
    __shared__ float As[2][16][128];
    __shared__ float Bs[2][16][128];
    const int tid  = threadIdx.x;
    const int wid  = tid >> 5;
    const int lane = tid & 31;
    const int wm   = wid >> 2;
    const int wn   = wid & 3;
    const int lr   = lane >> 2;
    const int lc   = lane & 3;
    const int m0   = blockIdx.y * 128;
    const int n0   = blockIdx.x * 128;
    const int aBase = wm*64 + lr*4;
    const int bBase = wn*32 + lc*4;

    const int aRow0 = tid >> 1;
    const int aCol0 = (tid & 1) << 3;
    const int bRow0 = tid >> 5;
    const int bCol0 = (tid & 31) << 2;

    const float* ApA = g_Y + (size_t)(m0 + aRow0) * DMODEL + aCol0;
    const float* BpA = W + (size_t)bRow0 * DMODEL + n0 + bCol0;
    const float* BpB = W + (size_t)(bRow0 + 8) * DMODEL + n0 + bCol0;

    uint64_t acc2[8][4];
    #pragma unroll
    for (int i = 0; i < 8; i++)
        #pragma unroll
        for (int jp = 0; jp < 4; jp++) acc2[i][jp] = 0ull;

    {
        float4 a0 = *(const float4*)(ApA);
        float4 a1 = *(const float4*)(ApA + 4);
        float4 b0 = *(const float4*)(BpA);
        float4 b1 = *(const float4*)(BpB);
        As[0][aCol0+0][aRow0] = a0.x;
        As[0][aCol0+1][aRow0] = a0.y;
        As[0][aCol0+2][aRow0] = a0.z;
        As[0][aCol0+3][aRow0] = a0.w;
        As[0][aCol0+4][aRow0] = a1.x;
        As[0][aCol0+5][aRow0] = a1.y;
        As[0][aCol0+6][aRow0] = a1.z;
        As[0][aCol0+7][aRow0] = a1.w;
        *(float4*)&Bs[0][bRow0][bCol0]     = b0;
        *(float4*)&Bs[0][bRow0 + 8][bCol0] = b1;
    }
    __syncthreads();

    const int NT = DMODEL / 16;
    for (int t = 0; t < NT; t++) {
        const int buf = t & 1;
        float4 a0n, a1n, b0n, b1n;
        if (t + 1 < NT) {
            const int k0 = (t + 1) * 16;
            a0n = *(const float4*)(ApA + k0);
            a1n = *(const float4*)(ApA + k0 + 4);
            b0n = *(const float4*)(BpA + (size_t)k0 * DMODEL);
            b1n = *(const float4*)(BpB + (size_t)k0 * DMODEL);
        }
        #pragma unroll
        for (int kk = 0; kk < 16; kk++) {
            float a[8], b[8];
            *(float4*)&a[0] = *(const float4*)&As[buf][kk][aBase];
            *(float4*)&a[4] = *(const float4*)&As[buf][kk][aBase + 32];
            *(float4*)&b[0] = *(const float4*)&Bs[buf][kk][bBase];
            *(float4*)&b[4] = *(const float4*)&Bs[buf][kk][bBase + 16];
            uint64_t b2[4];
            #pragma unroll
            for (int jp = 0; jp < 4; jp++) b2[jp] = f2pk(b[2*jp], b[2*jp+1]);
            #pragma unroll
            for (int i = 0; i < 8; i++) {
                const uint64_t a2 = f2pk(a[i], a[i]);
                #pragma unroll
                for (int jp = 0; jp < 4; jp++)
                    ffma2(acc2[i][jp], a2, b2[jp]);
            }
        }
        if (t + 1 < NT) {
            const int nb = buf ^ 1;
            As[nb][aCol0+0][aRow0] = a0n.x;
            As[nb][aCol0+1][aRow0] = a0n.y;
            As[nb][aCol0+2][aRow0] = a0n.z;
            As[nb][aCol0+3][aRow0] = a0n.w;
            As[nb][aCol0+4][aRow0] = a1n.x;
            As[nb][aCol0+5][aRow0] = a1n.y;
            As[nb][aCol0+6][aRow0] = a1n.z;
            As[nb][aCol0+7][aRow0] = a1n.w;
            *(float4*)&Bs[nb][bRow0][bCol0]     = b0n;
            *(float4*)&Bs[nb][bRow0 + 8][bCol0] = b1n;
        }
        __syncthreads();
    }

    #pragma unroll
    for (int i = 0; i < 8; i++) {
        float r8[8];
        #pragma unroll
        for (int jp = 0; jp < 4; jp++) f2unpk(acc2[i][jp], r8[2*jp], r8[2*jp+1]);
        const int m = m0 + aBase + ((i < 4) ? i : (28 + i));
        #pragma unroll
        for (int j4 = 0; j4 < 8; j4 += 4) {
            const int n = n0 + bBase + ((j4 == 0) ? 0 : 16);
            float4 ov;
            ov.x = r8[j4+0] + bias[n+0];
            ov.y = r8[j4+1] + bias[n+1];
            ov.z = r8[j4+2] + bias[n+2];
            ov.w = r8[j4+3] + bias[n+3];
            *(float4*)&out[(size_t)m * DMODEL + n] = ov;
        }
    }
}

// ---------------------------------------------------------------------------
extern "C" void kernel_launch(void* const* d_in, const int* in_sizes, int n_in,
                              void* d_out, int out_size)
{
    const float* x      = (const float*)d_in[0];
    const float* W_attn = (const float*)d_in[1];
    const float* b_attn = (const float*)d_in[2];
    const float* W_proj = (const float*)d_in[3];
    const float* b_proj = (const float*)d_in[4];
    const float* Er     = (const float*)d_in[5];
    float* out = (float*)d_out;

    (void)in_sizes; (void)n_in; (void)out_size;

    cudaFuncSetAttribute(attn_kernel,
                         cudaFuncAttributeMaxDynamicSharedMemorySize, AT_SMEM);

    gemm_qkv_kernel<<<dim3(24, 64), 256>>>(x, W_attn, b_attn);
    attn_kernel<<<dim3(64, 16), 256, AT_SMEM>>>(Er);
    gemm_proj_kernel<<<dim3(8, 64), 256>>>(W_proj, b_proj, out);
}